// round 16
// baseline (speedup 1.0000x reference)
#include <cuda_runtime.h>
#include <cuda_bf16.h>
#include <cuda_fp16.h>
#include <float.h>
#include <stdint.h>

#define N_NODES 100000
#define N_EDGES 1600000
#define D 128
#define KDIM 256

// ---------------------------------------------------------------------------
// Device scratch (static per harness rules).
// g_deg relies on BSS zero-init; fused_kernel re-zeros it after use.
// ---------------------------------------------------------------------------
__device__ int   g_deg[N_NODES];
__device__ int   g_off[N_NODES];
__device__ int   g_rank[N_EDGES];
__device__ int   g_adj[N_EDGES];
__device__ int   g_bsum[128];
__device__ int   g_bsumoff[128];
__device__ int   g_scan_ctr;
__device__ __align__(16) __half g_Hh[(size_t)N_NODES * D];   // fp16 copy of H
__device__ __align__(16) __half g_Wh16[128 * KDIM];          // W fp16 hi
__device__ __align__(16) __half g_Wl16[128 * KDIM];          // W fp16 lo (exact to 22 bits)

// ===========================================================================
// hist + H->fp16 + W->fp16 hi/lo conversion in ONE kernel (block-range split)
// ===========================================================================
#define NB_HIST 782                        // ceil(200000/256)
#define NB_CONV 6250                       // 12.8M H elems / 8 per thread / 256
#define NB_WSPL 16                         // 32768 W elems / 8 per thread / 256

__global__ void __launch_bounds__(256) hist_conv_kernel(const int* __restrict__ src,
                                                        const float* __restrict__ H,
                                                        const float* __restrict__ W) {
    if (blockIdx.x < NB_HIST) {
        int i = blockIdx.x * blockDim.x + threadIdx.x;   // over E/8
        if (i < N_EDGES / 8) {
            int4 s0 = reinterpret_cast<const int4*>(src)[i * 2 + 0];
            int4 s1 = reinterpret_cast<const int4*>(src)[i * 2 + 1];
            int4 r0, r1;
            r0.x = atomicAdd(&g_deg[s0.x], 1);
            r0.y = atomicAdd(&g_deg[s0.y], 1);
            r0.z = atomicAdd(&g_deg[s0.z], 1);
            r0.w = atomicAdd(&g_deg[s0.w], 1);
            r1.x = atomicAdd(&g_deg[s1.x], 1);
            r1.y = atomicAdd(&g_deg[s1.y], 1);
            r1.z = atomicAdd(&g_deg[s1.z], 1);
            r1.w = atomicAdd(&g_deg[s1.w], 1);
            reinterpret_cast<int4*>(g_rank)[i * 2 + 0] = r0;
            reinterpret_cast<int4*>(g_rank)[i * 2 + 1] = r1;
        }
    } else if (blockIdx.x < NB_HIST + NB_CONV) {
        size_t j = (size_t)(blockIdx.x - NB_HIST) * blockDim.x + threadIdx.x;
        size_t base = j * 8;
        if (base < (size_t)N_NODES * D) {
            float4 a = *reinterpret_cast<const float4*>(H + base);
            float4 b = *reinterpret_cast<const float4*>(H + base + 4);
            __half2 p0 = __float22half2_rn(make_float2(a.x, a.y));
            __half2 p1 = __float22half2_rn(make_float2(a.z, a.w));
            __half2 p2 = __float22half2_rn(make_float2(b.x, b.y));
            __half2 p3 = __float22half2_rn(make_float2(b.z, b.w));
            uint4 o;
            o.x = *reinterpret_cast<uint32_t*>(&p0);
            o.y = *reinterpret_cast<uint32_t*>(&p1);
            o.z = *reinterpret_cast<uint32_t*>(&p2);
            o.w = *reinterpret_cast<uint32_t*>(&p3);
            *reinterpret_cast<uint4*>(reinterpret_cast<uint8_t*>(g_Hh) + base * 2) = o;
        }
    } else {
        size_t j = (size_t)(blockIdx.x - NB_HIST - NB_CONV) * blockDim.x + threadIdx.x;
        size_t base = j * 8;
        if (base < (size_t)128 * KDIM) {
#pragma unroll
            for (int u = 0; u < 8; u++) {
                float v = W[base + u];
                __half h = __float2half_rn(v);
                g_Wh16[base + u] = h;
                g_Wl16[base + u] = __float2half_rn(v - __half2float(h));
            }
        }
    }
}

// ===========================================================================
// single-launch scan: warp-shuffle block scan + last-block scans the bsums
// ===========================================================================
__global__ void __launch_bounds__(1024) scan_kernel() {
    __shared__ int wsum[32];
    __shared__ int s2[128];
    __shared__ bool is_last;

    const int tid  = threadIdx.x;
    const int lane = tid & 31;
    const int wd   = tid >> 5;
    const int i    = blockIdx.x * 1024 + tid;

    int v = (i < N_NODES) ? g_deg[i] : 0;
    int x = v;
#pragma unroll
    for (int d = 1; d < 32; d <<= 1) {
        int t = __shfl_up_sync(0xffffffffu, x, d);
        if (lane >= d) x += t;
    }
    if (lane == 31) wsum[wd] = x;
    __syncthreads();
    if (wd == 0) {
        int y = wsum[lane];
#pragma unroll
        for (int d = 1; d < 32; d <<= 1) {
            int t = __shfl_up_sync(0xffffffffu, y, d);
            if (lane >= d) y += t;
        }
        wsum[lane] = y;
    }
    __syncthreads();
    int incl = x + (wd ? wsum[wd - 1] : 0);
    if (i < N_NODES) g_off[i] = incl - v;
    if (tid == 1023) g_bsum[blockIdx.x] = incl;

    __threadfence();
    if (tid == 0) is_last = (atomicAdd(&g_scan_ctr, 1) == (int)gridDim.x - 1);
    __syncthreads();

    if (is_last) {
        int b = (tid < 128 && tid < (int)gridDim.x) ? g_bsum[tid] : 0;
        if (tid < 128) s2[tid] = b;
        __syncthreads();
        for (int ofs = 1; ofs < 128; ofs <<= 1) {
            int t = (tid < 128 && tid >= ofs) ? s2[tid - ofs] : 0;
            __syncthreads();
            if (tid < 128) s2[tid] += t;
            __syncthreads();
        }
        if (tid < 128) g_bsumoff[tid] = s2[tid] - b;
        if (tid == 0) g_scan_ctr = 0;
    }
}

// ===========================================================================
// atomic-free scatter; triggers dependent (fused) launch at entry (PDL)
// ===========================================================================
__global__ void __launch_bounds__(256) fill_adj_kernel(const int* __restrict__ src,
                                                       const int* __restrict__ dst) {
    asm volatile("griddepcontrol.launch_dependents;");
    int i = blockIdx.x * blockDim.x + threadIdx.x;
    if (i < N_EDGES / 8) {
#pragma unroll
        for (int h = 0; h < 2; h++) {
            int4 s = reinterpret_cast<const int4*>(src)[i * 2 + h];
            int4 d = reinterpret_cast<const int4*>(dst)[i * 2 + h];
            int4 r = reinterpret_cast<const int4*>(g_rank)[i * 2 + h];
            g_adj[g_off[s.x] + g_bsumoff[s.x >> 10] + r.x] = d.x;
            g_adj[g_off[s.y] + g_bsumoff[s.y >> 10] + r.y] = d.y;
            g_adj[g_off[s.z] + g_bsumoff[s.z >> 10] + r.z] = d.z;
            g_adj[g_off[s.w] + g_bsumoff[s.w >> 10] + r.w] = d.w;
        }
    }
}

// ===========================================================================
// Fused GEMM + aggregate, all-fp16 2-pass MMA.
// A-H half staged ONCE (32 KB); B double-buffered via cp.async.ca (L1 kept).
// ===========================================================================
__device__ __forceinline__ uint32_t smem_u32(const void* p) {
    uint32_t a;
    asm("{ .reg .u64 t; cvta.to.shared.u64 t, %1; cvt.u32.u64 %0, t; }"
        : "=r"(a) : "l"(p));
    return a;
}

__device__ __forceinline__ uint32_t sw64(uint32_t b) { return b ^ ((b >> 3) & 0x30); }

__device__ __forceinline__ void cp16(uint32_t dst, const void* src) {
    asm volatile("cp.async.ca.shared.global [%0], [%1], 16;"
                 :: "r"(dst), "l"(src));
}

__device__ __forceinline__ void ldsm_x4(uint32_t& r0, uint32_t& r1, uint32_t& r2,
                                        uint32_t& r3, uint32_t addr) {
    asm volatile("ldmatrix.sync.aligned.m8n8.x4.shared.b16 {%0,%1,%2,%3}, [%4];"
                 : "=r"(r0), "=r"(r1), "=r"(r2), "=r"(r3) : "r"(addr));
}

__device__ __forceinline__ void mma_f16(float* c, uint32_t a0, uint32_t a1,
                                        uint32_t a2, uint32_t a3,
                                        uint32_t b0, uint32_t b1) {
    asm volatile(
        "mma.sync.aligned.m16n8k16.row.col.f32.f16.f16.f32 "
        "{%0,%1,%2,%3},{%4,%5,%6,%7},{%8,%9},{%0,%1,%2,%3};"
        : "+f"(c[0]), "+f"(c[1]), "+f"(c[2]), "+f"(c[3])
        : "r"(a0), "r"(a1), "r"(a2), "r"(a3), "r"(b0), "r"(b1));
}

__device__ __forceinline__ void hmax2_acc(uint2& m, uint2 v) {
    __half2 ma = *reinterpret_cast<__half2*>(&m.x);
    __half2 mb = *reinterpret_cast<__half2*>(&m.y);
    ma = __hmax2(ma, *reinterpret_cast<const __half2*>(&v.x));
    mb = __hmax2(mb, *reinterpret_cast<const __half2*>(&v.y));
    m.x = *reinterpret_cast<uint32_t*>(&ma);
    m.y = *reinterpret_cast<uint32_t*>(&mb);
}

// dynamic smem layout (96 KB total):
//   [0,     32768): agg[4 chunks][8KB fp16]
//   [32768, 65536): A full H-half [4 chunks][8KB fp16]  (staged once)
//   [65536, 73728): Bh buf0     [73728, 81920): Bl buf0
//   [81920, 90112): Bh buf1     [90112, 98304): Bl buf1
#define SM_AGG   0
#define SM_A     32768
#define SM_BH0   65536
#define SM_BL0   73728
#define SM_BH1   81920
#define SM_BL1   90112
#define SM_TOTAL 98304

#define NT 512

struct GemmCtx {
    uint8_t* smem;
    int mblk, tid, lane, warp_m, warp_n, lsub, lr;
    uint32_t bA, bBh[2], bBl[2], bAgg;
};

// aggregate 8 rows per warp from fp16 H copy; raw fp16 stored to smem
__device__ __forceinline__ void do_aggregate(const GemmCtx& g) {
    const int lane = g.lane;
    const int wid  = g.tid >> 5;
    const int q  = lane & 7;
    const int ch = lane >> 3;
    uint8_t* agg = g.smem + SM_AGG + ch * 8192;

    const uint8_t* Hh = reinterpret_cast<const uint8_t*>(g_Hh);
    const uint32_t lane_off = (uint32_t)lane * 8;

    const uint32_t NEGINF2 = 0xFC00FC00u;

    for (int i = 0; i < 8; i++) {
        int mloc  = wid * 8 + i;
        int gnode = g.mblk + mloc;
        uint2 m = make_uint2(NEGINF2, NEGINF2);
        int deg = 0;
        if (gnode < N_NODES) {
            int off = g_off[gnode] + g_bsumoff[gnode >> 10];
            deg = g_deg[gnode];
            int j = 0;
            for (; j + 8 <= deg; j += 8) {
                uint2 v0 = *reinterpret_cast<const uint2*>(Hh + (size_t)g_adj[off + j + 0] * 256 + lane_off);
                uint2 v1 = *reinterpret_cast<const uint2*>(Hh + (size_t)g_adj[off + j + 1] * 256 + lane_off);
                uint2 v2 = *reinterpret_cast<const uint2*>(Hh + (size_t)g_adj[off + j + 2] * 256 + lane_off);
                uint2 v3 = *reinterpret_cast<const uint2*>(Hh + (size_t)g_adj[off + j + 3] * 256 + lane_off);
                uint2 v4 = *reinterpret_cast<const uint2*>(Hh + (size_t)g_adj[off + j + 4] * 256 + lane_off);
                uint2 v5 = *reinterpret_cast<const uint2*>(Hh + (size_t)g_adj[off + j + 5] * 256 + lane_off);
                uint2 v6 = *reinterpret_cast<const uint2*>(Hh + (size_t)g_adj[off + j + 6] * 256 + lane_off);
                uint2 v7 = *reinterpret_cast<const uint2*>(Hh + (size_t)g_adj[off + j + 7] * 256 + lane_off);
                hmax2_acc(m, v0); hmax2_acc(m, v1); hmax2_acc(m, v2); hmax2_acc(m, v3);
                hmax2_acc(m, v4); hmax2_acc(m, v5); hmax2_acc(m, v6); hmax2_acc(m, v7);
            }
            for (; j < deg; j++) {
                uint2 v = *reinterpret_cast<const uint2*>(Hh + (size_t)g_adj[off + j] * 256 + lane_off);
                hmax2_acc(m, v);
            }
        }
        if (deg == 0) m = make_uint2(0u, 0u);
        *reinterpret_cast<uint2*>(agg + sw64((uint32_t)(mloc * 64 + q * 8))) = m;
    }
}

// stage the ENTIRE A-H half (128 rows x 128 k fp16 = 32 KB), once
__device__ __forceinline__ void stage_a_all(const GemmCtx& g) {
#pragma unroll
    for (int p = 0; p < 4; p++) {
        int i = p * NT + g.tid;            // 2048 x 16B blocks
        int m = i >> 4;                    // row (16 blocks per 256B row)
        int u = i & 15;                    // 16B block within row
        int chunk = u >> 2, q = u & 3;
        int gm = g.mblk + m;
        if (gm >= N_NODES) gm = N_NODES - 1;   // clamp; rows masked at store
        cp16(g.bA + chunk * 8192 + sw64((uint32_t)(m * 64 + q * 16)),
             reinterpret_cast<const uint8_t*>(g_Hh) + (size_t)gm * 256 + u * 16);
    }
}

// stage B chunk c into buffer c&1 (one commit group per chunk)
__device__ __forceinline__ void stage_b(const GemmCtx& g, int c) {
    const int idx = g.tid >> 2, u = g.tid & 3;
    const uint32_t sb = sw64((uint32_t)(idx * 64 + u * 16));
    const int buf = c & 1;
    size_t so = ((size_t)idx * KDIM + c * 32) * 2 + u * 16;
    cp16(g.bBh[buf] + sb, reinterpret_cast<const uint8_t*>(g_Wh16) + so);
    cp16(g.bBl[buf] + sb, reinterpret_cast<const uint8_t*>(g_Wl16) + so);
}

__device__ __forceinline__ void mma_chunk(const GemmCtx& g, int c, float acc[2][4][4]) {
    const int buf = c & 1;
    const uint32_t aBase = (c < 4) ? (g.bA + (uint32_t)c * 8192u)
                                   : (g.bAgg + (uint32_t)(c - 4) * 8192u);
    const uint32_t bh = g.bBh[buf], bl = g.bBl[buf];

#pragma unroll
    for (int ks = 0; ks < 2; ks++) {
        const int k0 = ks * 16;
        uint32_t A[2][4];
#pragma unroll
        for (int f = 0; f < 2; f++) {
            int row = g.warp_m * 32 + f * 16 + (g.lsub & 1) * 8 + g.lr;
            int kb  = k0 + (g.lsub >> 1) * 8;
            uint32_t ofs = sw64((uint32_t)(row * 64 + kb * 2));
            ldsm_x4(A[f][0], A[f][1], A[f][2], A[f][3], aBase + ofs);
        }
#pragma unroll
        for (int np = 0; np < 2; np++) {
            int n  = g.warp_n * 32 + np * 16 + (g.lsub >> 1) * 8 + g.lr;
            int kb = k0 + (g.lsub & 1) * 8;
            uint32_t ofs = sw64((uint32_t)(n * 64 + kb * 2));
            uint32_t Bh[4], Bl[4];
            ldsm_x4(Bh[0], Bh[1], Bh[2], Bh[3], bh + ofs);
            ldsm_x4(Bl[0], Bl[1], Bl[2], Bl[3], bl + ofs);
#pragma unroll
            for (int f = 0; f < 2; f++) {
                mma_f16(acc[f][np * 2 + 0], A[f][0], A[f][1], A[f][2], A[f][3], Bh[0], Bh[1]);
                mma_f16(acc[f][np * 2 + 1], A[f][0], A[f][1], A[f][2], A[f][3], Bh[2], Bh[3]);
                mma_f16(acc[f][np * 2 + 0], A[f][0], A[f][1], A[f][2], A[f][3], Bl[0], Bl[1]);
                mma_f16(acc[f][np * 2 + 1], A[f][0], A[f][1], A[f][2], A[f][3], Bl[2], Bl[3]);
            }
        }
    }
}

__global__ void __launch_bounds__(NT, 2) fused_kernel(
    const float* __restrict__ bias,
    float* __restrict__ out)
{
    extern __shared__ __align__(16) uint8_t smem[];

    GemmCtx g;
    g.smem   = smem;
    g.tid    = threadIdx.x;
    g.lane   = g.tid & 31;
    g.mblk   = blockIdx.x * 128;
    int wid  = g.tid >> 5;
    g.warp_m = wid >> 2;
    g.warp_n = wid & 3;
    g.lsub   = g.lane >> 3;
    g.lr     = g.lane & 7;
    g.bA     = smem_u32(smem + SM_A);
    g.bBh[0] = smem_u32(smem + SM_BH0);
    g.bBl[0] = smem_u32(smem + SM_BL0);
    g.bBh[1] = smem_u32(smem + SM_BH1);
    g.bBl[1] = smem_u32(smem + SM_BL1);
    g.bAgg   = smem_u32(smem + SM_AGG);

    float acc[2][4][4];
#pragma unroll
    for (int f = 0; f < 2; f++)
#pragma unroll
        for (int t = 0; t < 4; t++)
#pragma unroll
            for (int i = 0; i < 4; i++) acc[f][t][i] = 0.f;

    // prologue group 0: all of A + B(0)
    stage_a_all(g);
    stage_b(g, 0);
    asm volatile("cp.async.commit_group;");

    // pipeline: stage B(c+1) while MMA(c); aggregate at the H->agg boundary.
    // g_Hh/g_Wh16/g_Wl16 complete (3 kernels upstream); only g_adj in flight.
    for (int c = 0; c < 8; c++) {
        if (c < 7) {
            stage_b(g, c + 1);
            asm volatile("cp.async.commit_group;");
        }
        if (c == 4) {
            cudaGridDependencySynchronize();
            do_aggregate(g);
        }
        if (c < 7) asm volatile("cp.async.wait_group 1;");
        else       asm volatile("cp.async.wait_group 0;");
        __syncthreads();
        mma_chunk(g, c, acc);
        __syncthreads();
    }

    // ---- epilogue: add bias, store ----
    const int mbase = g.mblk + g.warp_m * 32 + (g.lane >> 2);
#pragma unroll
    for (int f = 0; f < 2; f++) {
        int row0 = mbase + f * 16;
        int row1 = row0 + 8;
#pragma unroll
        for (int t = 0; t < 4; t++) {
            int col = g.warp_n * 32 + t * 8 + (g.lane & 3) * 2;
            float2 bv = *reinterpret_cast<const float2*>(bias + col);
            if (row0 < N_NODES) {
                float2 o = make_float2(acc[f][t][0] + bv.x, acc[f][t][1] + bv.y);
                *reinterpret_cast<float2*>(out + (size_t)row0 * D + col) = o;
            }
            if (row1 < N_NODES) {
                float2 o = make_float2(acc[f][t][2] + bv.x, acc[f][t][3] + bv.y);
                *reinterpret_cast<float2*>(out + (size_t)row1 * D + col) = o;
            }
        }
    }

    // ---- self-restore g_deg to 0 for the next replay (deterministic) ----
    for (int i = g.tid; i < 128; i += NT) {
        int gn = g.mblk + i;
        if (gn < N_NODES) g_deg[gn] = 0;
    }
}

// ===========================================================================
// Launch: 3 prologue kernels + fused (PDL trigger lives in fill_adj)
// ===========================================================================
extern "C" void kernel_launch(void* const* d_in, const int* in_sizes, int n_in,
                              void* d_out, int out_size) {
    const float* H   = (const float*)d_in[0];
    const int*   src = (const int*)d_in[1];
    const int*   dst = (const int*)d_in[2];
    const float* W   = (const float*)d_in[3];
    const float* b   = (const float*)d_in[4];
    float*       out = (float*)d_out;

    cudaFuncSetAttribute(fused_kernel,
                         cudaFuncAttributeMaxDynamicSharedMemorySize, SM_TOTAL);

    const int nb_scan = (N_NODES + 1023) / 1024;   // 98
    const int nb_gemm = (N_NODES + 127) / 128;     // 782
    const int nb_e8   = (N_EDGES / 8 + 255) / 256; // 782

    hist_conv_kernel<<<NB_HIST + NB_CONV + NB_WSPL, 256>>>(src, H, W);
    scan_kernel<<<nb_scan, 1024>>>();
    fill_adj_kernel<<<nb_e8, 256>>>(src, dst);

    cudaLaunchConfig_t cfg = {};
    cfg.gridDim = dim3((unsigned)nb_gemm);
    cfg.blockDim = dim3(NT);
    cfg.dynamicSmemBytes = SM_TOTAL;
    cfg.stream = 0;
    cudaLaunchAttribute attrs[1];
    attrs[0].id = cudaLaunchAttributeProgrammaticStreamSerialization;
    attrs[0].val.programmaticStreamSerializationAllowed = 1;
    cfg.attrs = attrs;
    cfg.numAttrs = 1;
    cudaLaunchKernelEx(&cfg, fused_kernel, b, out);
}